// round 4
// baseline (speedup 1.0000x reference)
#include <cuda_runtime.h>
#include <float.h>

// NormmaxBisect, alpha = 1.5, n_iter = 50, d = 2048.
// p = max(x-tau,0)^2 ; p^alpha = max(x-tau,0)^3 ; tau in (max-1, max-d^-0.5].
// Only elements with x > blockmax-1 can be nonzero -> zero-fill + scatter.
// Gather is WARP-LOCAL against warpmax-1 (a superset: warpmax <= blockmax, and
// since tau is always clamped >= blockmax-1, extra candidates contribute exactly
// 0 through fmaxf). This needs only ONE block barrier.
// Root found by Newton on f(tau) = sum c^3 - 1 (convex, decreasing) with early
// exit; lands within ~1 ulp of the reference's 50-step fp32 bisection.

constexpr int   D       = 2048;
constexpr int   THREADS = 256;
constexpr int   NW      = THREADS / 32;   // 8 warps
constexpr int   SLOT    = 32;             // candidate slots per warp (E[count]~8)
constexpr float TAU_HI_OFF = 0.022097086912079612f;  // (1/2048)^0.5
constexpr float SENT = -1.0e30f;          // contributes exactly 0 via fmaxf

__global__ void __launch_bounds__(THREADS)
normmax_kernel(const float* __restrict__ X, float* __restrict__ Out)
{
    __shared__ float s_cand[THREADS];     // NW regions of SLOT slots
    __shared__ int   s_pos[THREADS];
    __shared__ float s_wmax[NW];
    __shared__ int   s_cnt[NW];

    const size_t base = (size_t)blockIdx.x * D;
    const float4* __restrict__ xin  = reinterpret_cast<const float4*>(X + base);
    float4* __restrict__       xout = reinterpret_cast<float4*>(Out + base);

    const int t    = threadIdx.x;
    const int lane = t & 31;
    const int wid  = t >> 5;

    // Pre-pad candidate array; per-warp counter init. (Each warp only ever
    // touches its own region/counter before the block barrier.)
    s_cand[t] = SENT;
    if (lane == 0) s_cnt[wid] = 0;

    // ---- Load 8 elems/thread (streaming), zero-fill output early ----
    float4 v0 = __ldcs(xin + t);
    float4 v1 = __ldcs(xin + t + THREADS);
    const float4 z4 = make_float4(0.f, 0.f, 0.f, 0.f);
    __stcs(xout + t, z4);
    __stcs(xout + t + THREADS, z4);

    float x0 = v0.x, x1 = v0.y, x2 = v0.z, x3 = v0.w;
    float x4 = v1.x, x5 = v1.y, x6 = v1.z, x7 = v1.w;

    // ---- Warp max (butterfly -> all lanes) ----
    float m = fmaxf(fmaxf(fmaxf(x0, x1), fmaxf(x2, x3)),
                    fmaxf(fmaxf(x4, x5), fmaxf(x6, x7)));
#pragma unroll
    for (int o = 16; o; o >>= 1)
        m = fmaxf(m, __shfl_xor_sync(0xffffffffu, m, o));
    if (lane == 0) s_wmax[wid] = m;
    const float wthresh = m - 1.0f;

    // ---- Warp-local gather into this warp's region ----
    unsigned mm = 0;
    mm |= (x0 > wthresh) ? 1u   : 0u;
    mm |= (x1 > wthresh) ? 2u   : 0u;
    mm |= (x2 > wthresh) ? 4u   : 0u;
    mm |= (x3 > wthresh) ? 8u   : 0u;
    mm |= (x4 > wthresh) ? 16u  : 0u;
    mm |= (x5 > wthresh) ? 32u  : 0u;
    mm |= (x6 > wthresh) ? 64u  : 0u;
    mm |= (x7 > wthresh) ? 128u : 0u;
    __syncwarp();                         // counter init + pad visible in-warp
    if (mm) {                             // ~25% of threads
        int p = atomicAdd(&s_cnt[wid], __popc(mm));
        const int rb = wid * SLOT;
        float xv[8] = {x0, x1, x2, x3, x4, x5, x6, x7};
#pragma unroll
        for (int i = 0; i < 8; ++i) {
            if ((mm >> i) & 1) {
                if (p < SLOT) {
                    s_cand[rb + p] = xv[i];
                    s_pos[rb + p]  = 4 * t + (i >> 2) * (4 * THREADS) + (i & 3);
                }
                ++p;
            }
        }
    }
    __syncthreads();   // the ONLY block barrier

    // One warp finishes the row; the rest retire.
    if (wid != (int)(blockIdx.x & (unsigned)(NW - 1))) return;

    // Block max + overflow check (serial over 8, tiny)
    float bmax = s_wmax[0];
    bool  ok   = (s_cnt[0] <= SLOT);
#pragma unroll
    for (int w = 1; w < NW; ++w) {
        bmax = fmaxf(bmax, s_wmax[w]);
        ok   = ok && (s_cnt[w] <= SLOT);
    }
    const float thresh = bmax - 1.0f;
    const float tau_hi = bmax - TAU_HI_OFF;   // f(tau_hi) < 0 always

    if (ok) {
        // ---- Newton, lane-parallel over the 256 (SENT-padded) slots ----
        float cv[NW];
#pragma unroll
        for (int w = 0; w < NW; ++w) cv[w] = s_cand[w * SLOT + lane];

        float tau = thresh;                    // f(thresh) >= 0
#pragma unroll 1
        for (int it = 0; it < 8; ++it) {
            float a = 0.f, b = 0.f;
#pragma unroll
            for (int w = 0; w < NW; ++w) {
                float c = fmaxf(cv[w] - tau, 0.f);
                float q = c * c;
                a += q;
                b = fmaf(q, c, b);
            }
#pragma unroll
            for (int o = 16; o; o >>= 1) {     // two independent chains pipeline
                a += __shfl_xor_sync(0xffffffffu, a, o);
                b += __shfl_xor_sync(0xffffffffu, b, o);
            }
            // f = b-1, f' = -3a  (a >= (bmax-tau)^2 > 0 while tau <= tau_hi)
            float nt = tau + (b - 1.0f) / (3.0f * a);
            nt = fminf(fmaxf(nt, thresh), tau_hi);
            if (nt == tau) break;              // converged (uniform)
            tau = nt;
        }

        // ---- Final S = sum c^2 and scatter ----
        float q[NW];
        float S = 0.f;
#pragma unroll
        for (int w = 0; w < NW; ++w) {
            float c = fmaxf(cv[w] - tau, 0.f);
            q[w] = c * c;
            S += q[w];
        }
#pragma unroll
        for (int o = 16; o; o >>= 1) S += __shfl_xor_sync(0xffffffffu, S, o);
        const float invS = 1.0f / S;

#pragma unroll
        for (int w = 0; w < NW; ++w)
            if (q[w] > 0.f)                    // SENT / clamped slots write nothing
                Out[base + s_pos[w * SLOT + lane]] = q[w] * invS;
    } else {
        // ---- Dense fallback (statistically never): exact reference bisection,
        //      single warp, row re-read through L2. ----
        float tau_lo = thresh;
        float dm     = tau_hi - tau_lo;
        float tau_m  = tau_lo;
        for (int it = 0; it < 50; ++it) {
            dm *= 0.5f;
            tau_m = tau_lo + dm;
            if (tau_m == tau_lo) break;
            float s = 0.f;
            for (int j = lane; j < D; j += 32) {
                float c = fmaxf(X[base + j] - tau_m, 0.f);
                s = fmaf(c * c, c, s);
            }
#pragma unroll
            for (int o = 16; o; o >>= 1) s += __shfl_xor_sync(0xffffffffu, s, o);
            if (s >= 1.0f) tau_lo = tau_m;
        }
        float S = 0.f;
        for (int j = lane; j < D; j += 32) {
            float c = fmaxf(X[base + j] - tau_m, 0.f);
            S = fmaf(c, c, S);
        }
#pragma unroll
        for (int o = 16; o; o >>= 1) S += __shfl_xor_sync(0xffffffffu, S, o);
        const float invS = 1.0f / S;
        for (int j = lane; j < D; j += 32) {
            float c = fmaxf(X[base + j] - tau_m, 0.f);
            Out[base + j] = c * c * invS;
        }
    }
}

extern "C" void kernel_launch(void* const* d_in, const int* in_sizes, int n_in,
                              void* d_out, int out_size) {
    const float* X = (const float*)d_in[0];
    float* Out = (float*)d_out;
    int nrows = out_size / D;
    normmax_kernel<<<nrows, THREADS>>>(X, Out);
}

// round 5
// speedup vs baseline: 1.2827x; 1.2827x over previous
#include <cuda_runtime.h>
#include <float.h>

// NormmaxBisect, alpha = 1.5, n_iter = 50, d = 2048.
// p = max(x-tau,0)^2 ; p^alpha = max(x-tau,0)^3 ; tau in (max-1, max-d^-0.5].
// Only elements with x > blockmax-1 can be nonzero -> zero-fill + scatter.
// Root found by Newton on f(tau) = sum c^3 - 1 (convex, decreasing, start at
// f>=0 side => monotone quadratic convergence); lands within ~1 ulp of the
// reference's 50-step fp32 bisection. Tail runs serial-redundant in one warp:
// no shuffles, candidates read from SMEM (broadcast, conflict-free).

constexpr int   D       = 2048;
constexpr int   THREADS = 256;
constexpr int   CAP     = 128;                        // E[#candidates] ~ 25
constexpr float TAU_HI_OFF = 0.022097086912079612f;   // (1/2048)^0.5

__global__ void __launch_bounds__(THREADS)
normmax_kernel(const float* __restrict__ X, float* __restrict__ Out)
{
    __shared__ float s_cand[CAP];
    __shared__ int   s_pos[CAP];
    __shared__ float s_red[THREADS / 32];
    __shared__ int   s_cnt;

    const size_t base = (size_t)blockIdx.x * D;
    const float4* __restrict__ xin  = reinterpret_cast<const float4*>(X + base);
    float4* __restrict__       xout = reinterpret_cast<float4*>(Out + base);

    const int t    = threadIdx.x;
    const int lane = t & 31;
    const int wid  = t >> 5;
    if (t == 0) s_cnt = 0;

    // ---- Load 8 elems/thread (read-once: streaming), zero-fill output early ----
    float4 v0 = __ldcs(xin + t);
    float4 v1 = __ldcs(xin + t + THREADS);
    const float4 z4 = make_float4(0.f, 0.f, 0.f, 0.f);
    xout[t]           = z4;
    xout[t + THREADS] = z4;

    float x0 = v0.x, x1 = v0.y, x2 = v0.z, x3 = v0.w;
    float x4 = v1.x, x5 = v1.y, x6 = v1.z, x7 = v1.w;

    float m = fmaxf(fmaxf(fmaxf(x0, x1), fmaxf(x2, x3)),
                    fmaxf(fmaxf(x4, x5), fmaxf(x6, x7)));
#pragma unroll
    for (int o = 16; o; o >>= 1)
        m = fmaxf(m, __shfl_xor_sync(0xffffffffu, m, o));
    if (lane == 0) s_red[wid] = m;
    __syncthreads();

    float maxval = s_red[0];
#pragma unroll
    for (int w = 1; w < THREADS / 32; ++w) maxval = fmaxf(maxval, s_red[w]);
    const float thresh = maxval - 1.0f;

    // ---- Gather candidates: per-thread bitmask + one atomic per hit-thread ----
    unsigned mm = 0;
    mm |= (x0 > thresh) ? 1u   : 0u;
    mm |= (x1 > thresh) ? 2u   : 0u;
    mm |= (x2 > thresh) ? 4u   : 0u;
    mm |= (x3 > thresh) ? 8u   : 0u;
    mm |= (x4 > thresh) ? 16u  : 0u;
    mm |= (x5 > thresh) ? 32u  : 0u;
    mm |= (x6 > thresh) ? 64u  : 0u;
    mm |= (x7 > thresh) ? 128u : 0u;
    if (mm) {   // ~10% of threads
        int p = atomicAdd(&s_cnt, __popc(mm));
        float xv[8] = {x0, x1, x2, x3, x4, x5, x6, x7};
#pragma unroll
        for (int i = 0; i < 8; ++i) {
            if ((mm >> i) & 1) {
                if (p < CAP) {
                    s_cand[p] = xv[i];
                    s_pos[p]  = 4 * t + (i >> 2) * (4 * THREADS) + (i & 3);
                }
                ++p;
            }
        }
    }
    __syncthreads();
    const int n = s_cnt;

    // One warp finishes the row (choice balanced across SMSPs); others retire.
    if (wid != (int)(blockIdx.x & (unsigned)(THREADS / 32 - 1))) return;

    const float tau_hi = maxval - TAU_HI_OFF;   // f(tau_hi) < 0 always

    if (n <= CAP) {
        // ---- Serial-redundant Newton: all lanes compute the identical sums
        //      straight from SMEM (broadcast LDS). No shuffles anywhere. ----
        float tau = thresh;                      // f(thresh) >= 0
#pragma unroll 1
        for (int it = 0; it < 8; ++it) {
            float a0 = 0.f, a1 = 0.f, a2 = 0.f, a3 = 0.f;
            float b0 = 0.f, b1 = 0.f, b2 = 0.f, b3 = 0.f;
            int j = 0;
            for (; j + 4 <= n; j += 4) {
                float c0 = fmaxf(s_cand[j]     - tau, 0.f), q0 = c0 * c0;
                float c1 = fmaxf(s_cand[j + 1] - tau, 0.f), q1 = c1 * c1;
                float c2 = fmaxf(s_cand[j + 2] - tau, 0.f), q2 = c2 * c2;
                float c3 = fmaxf(s_cand[j + 3] - tau, 0.f), q3 = c3 * c3;
                a0 += q0; b0 = fmaf(q0, c0, b0);
                a1 += q1; b1 = fmaf(q1, c1, b1);
                a2 += q2; b2 = fmaf(q2, c2, b2);
                a3 += q3; b3 = fmaf(q3, c3, b3);
            }
            for (; j < n; ++j) {
                float c = fmaxf(s_cand[j] - tau, 0.f), q = c * c;
                a0 += q; b0 = fmaf(q, c, b0);
            }
            float a = (a0 + a1) + (a2 + a3);     // sum c^2
            float b = (b0 + b1) + (b2 + b3);     // sum c^3
            // f = b-1, f' = -3a  (a >= (maxval-tau)^2 > 0 while tau <= tau_hi)
            float nt = tau + (b - 1.0f) / (3.0f * a);
            nt = fminf(fmaxf(nt, thresh), tau_hi);
            if (nt == tau) break;                // converged (uniform)
            tau = nt;
        }

        // ---- Final S = sum c^2 (serial-redundant), then lane-strided scatter ----
        float S0 = 0.f, S1 = 0.f;
        for (int j = 0; j < n; ++j) {
            float c = fmaxf(s_cand[j] - tau, 0.f);
            if (j & 1) S1 = fmaf(c, c, S1); else S0 = fmaf(c, c, S0);
        }
        const float invS = 1.0f / (S0 + S1);

        for (int j = lane; j < n; j += 32) {
            float c = fmaxf(s_cand[j] - tau, 0.f);
            Out[base + s_pos[j]] = c * c * invS;
        }
    } else {
        // ---- Dense fallback (statistically never): exact reference bisection,
        //      single warp, row re-read through L2. ----
        float tau_lo = thresh;
        float dm     = tau_hi - tau_lo;
        float tau_m  = tau_lo;
        for (int it = 0; it < 50; ++it) {
            dm *= 0.5f;
            tau_m = tau_lo + dm;
            if (tau_m == tau_lo) break;
            float s = 0.f;
            for (int j = lane; j < D; j += 32) {
                float c = fmaxf(X[base + j] - tau_m, 0.f);
                s = fmaf(c * c, c, s);
            }
#pragma unroll
            for (int o = 16; o; o >>= 1) s += __shfl_xor_sync(0xffffffffu, s, o);
            if (s >= 1.0f) tau_lo = tau_m;
        }
        float S = 0.f;
        for (int j = lane; j < D; j += 32) {
            float c = fmaxf(X[base + j] - tau_m, 0.f);
            S = fmaf(c, c, S);
        }
#pragma unroll
        for (int o = 16; o; o >>= 1) S += __shfl_xor_sync(0xffffffffu, S, o);
        const float invS = 1.0f / S;
        for (int j = lane; j < D; j += 32) {
            float c = fmaxf(X[base + j] - tau_m, 0.f);
            Out[base + j] = c * c * invS;
        }
    }
}

extern "C" void kernel_launch(void* const* d_in, const int* in_sizes, int n_in,
                              void* d_out, int out_size) {
    const float* X = (const float*)d_in[0];
    float* Out = (float*)d_out;
    int nrows = out_size / D;
    normmax_kernel<<<nrows, THREADS>>>(X, Out);
}